// round 15
// baseline (speedup 1.0000x reference)
#include <cuda_runtime.h>
#include <cuda_bf16.h>
#include <cstdint>

typedef unsigned long long ull;

// ---------- packed f32x2 helpers (attention) ----------
__device__ __forceinline__ ull fma2(ull a, ull b, ull c) {
    ull d; asm("fma.rn.f32x2 %0, %1, %2, %3;" : "=l"(d) : "l"(a), "l"(b), "l"(c)); return d;
}
__device__ __forceinline__ ull add2(ull a, ull b) {
    ull d; asm("add.rn.f32x2 %0, %1, %2;" : "=l"(d) : "l"(a), "l"(b)); return d;
}
__device__ __forceinline__ ull mul2(ull a, ull b) {
    ull d; asm("mul.rn.f32x2 %0, %1, %2;" : "=l"(d) : "l"(a), "l"(b)); return d;
}
__device__ __forceinline__ ull pk(float lo, float hi) {
    ull r; asm("mov.b64 %0, {%1, %2};" : "=l"(r) : "f"(lo), "f"(hi)); return r;
}
__device__ __forceinline__ void upk(ull v, float& lo, float& hi) {
    asm("mov.b64 {%0, %1}, %2;" : "=f"(lo), "=f"(hi) : "l"(v));
}

// ---------- warp-MMA primitives ----------
#define SWZ(o) ((uint32_t)(o) ^ ((((uint32_t)(o)) >> 3) & 0x70u))

__device__ __forceinline__ uint32_t smem_u32(const void* p) {
    uint32_t a;
    asm("{ .reg .u64 t; cvta.to.shared.u64 t, %1; cvt.u32.u64 %0, t; }" : "=r"(a) : "l"(p));
    return a;
}
__device__ __forceinline__ void cp16(uint32_t dst, const void* src, uint32_t srcsz) {
    asm volatile("cp.async.ca.shared.global [%0], [%1], 16, %2;"
                 :: "r"(dst), "l"(src), "r"(srcsz) : "memory");
}
#define CP_COMMIT asm volatile("cp.async.commit_group;" ::: "memory")
#define CP_WAIT1  asm volatile("cp.async.wait_group 1;" ::: "memory")
#define CP_WAIT0  asm volatile("cp.async.wait_group 0;" ::: "memory")

#define LDSM4(d, a) \
    asm volatile("ldmatrix.sync.aligned.m8n8.x4.shared.b16 {%0,%1,%2,%3}, [%4];" \
                 : "=r"((d)[0]), "=r"((d)[1]), "=r"((d)[2]), "=r"((d)[3]) : "r"(a))

#define MMA16816(c, a, b0, b1) \
    asm volatile("mma.sync.aligned.m16n8k16.row.col.f32.bf16.bf16.f32 " \
                 "{%0,%1,%2,%3},{%4,%5,%6,%7},{%8,%9},{%0,%1,%2,%3};" \
                 : "+f"((c)[0]), "+f"((c)[1]), "+f"((c)[2]), "+f"((c)[3]) \
                 : "r"((a)[0]), "r"((a)[1]), "r"((a)[2]), "r"((a)[3]), \
                   "r"(b0), "r"(b1))

// ---------- scratch (device globals) ----------
__device__ __align__(128) __nv_bfloat16 g_xh[2097152], g_xl[2097152];     // [pix][256]
__device__ __align__(128) __nv_bfloat16 g_w3h[65536],   g_w3l[65536];     // [tap][oc][cin]
__device__ __align__(128) __nv_bfloat16 g_w5h[589824],  g_w5l[589824];
__device__ __align__(128) __nv_bfloat16 g_w7h[1638400], g_w7l[1638400];
__device__ __align__(128) __nv_bfloat16 g_wph[65536],   g_wpl[65536];
__device__ __align__(128) float g_q[2097152], g_k[2097152], g_v[2097152]; // [b*256+ch][1024]
__device__ __align__(128) __nv_bfloat16 g_aoh[2097152], g_aol[2097152];   // [pix][256]

// ---------- one fused split kernel (all 5 tensors by flat index) ----------
__device__ __forceinline__ void wsplit(const float* w, __nv_bfloat16* wh,
                                       __nv_bfloat16* wl, int idx, int taps) {
    int o = (idx >> 8) & 255;
    int i = idx & 255;
    int t = idx >> 16;
    float f = w[(o * 256 + i) * taps + t];
    __nv_bfloat16 h = __float2bfloat16(f);
    wh[idx] = h;
    wl[idx] = __float2bfloat16(f - __bfloat162float(h));
}
__global__ void fused_split(const float* __restrict__ x,  const float* __restrict__ w3,
                            const float* __restrict__ w5, const float* __restrict__ w7,
                            const float* __restrict__ wp,
                            __nv_bfloat16* xh, __nv_bfloat16* xl,
                            __nv_bfloat16* w3h, __nv_bfloat16* w3l,
                            __nv_bfloat16* w5h, __nv_bfloat16* w5l,
                            __nv_bfloat16* w7h, __nv_bfloat16* w7l,
                            __nv_bfloat16* wph, __nv_bfloat16* wpl) {
    int i = blockIdx.x * 256 + threadIdx.x;
    if (i < 2097152) {
        float f = x[i];
        __nv_bfloat16 h = __float2bfloat16(f);
        xh[i] = h;
        xl[i] = __float2bfloat16(f - __bfloat162float(h));
    } else if (i < 2162688) {
        wsplit(w3, w3h, w3l, i - 2097152, 1);
    } else if (i < 2752512) {
        wsplit(w5, w5h, w5l, i - 2162688, 9);
    } else if (i < 4390912) {
        wsplit(w7, w7h, w7l, i - 2752512, 25);
    } else {
        wsplit(wp, wph, wpl, i - 4390912, 1);
    }
}

// ---------- HMMA implicit-GEMM conv (bf16 3-term split; KC=32, occ 2) ----------
// D[128 pix, 128 oc] = sum over (tap, 32-ch chunk) of Ah*Bh + Ah*Bl + Al*Bh.
// Stage 32KB: Ah@0 Al@8K Bh@16K Bl@24K. Rows are 64B; two logical rows share one
// 128B swizzled smem row: o = (r>>1)*128 + (r&1)*64 + byte, then SW128.
// Double buffer = 64KB -> 2 CTAs/SM. 8 warps: warp_m=wid&3 (32 rows), warp_n=wid>>2 (64 cols).
template<int KS, bool TROUT>
__global__ __launch_bounds__(256, 2)
void conv_mma(const __nv_bfloat16* __restrict__ Ah, const __nv_bfloat16* __restrict__ Al,
              const __nv_bfloat16* __restrict__ Bh, const __nv_bfloat16* __restrict__ Bl,
              const float* __restrict__ bias, float* __restrict__ C)
{
    extern __shared__ char smem[];
    const uint32_t sb = smem_u32(smem);
    const int tid = threadIdx.x, wid = tid >> 5, lane = tid & 31;
    const int nb = blockIdx.x;      // oc block of 128 (0..1)
    const int mb = blockIdx.y;      // pixel block of 128 (0..63)
    const int p0 = mb * 128, bimg = p0 >> 10;
    const int wm = (wid & 3) * 32, wn = (wid >> 2) * 64;

    float acc[2][8][4];
#pragma unroll
    for (int mi = 0; mi < 2; ++mi)
#pragma unroll
        for (int n8 = 0; n8 < 8; ++n8)
#pragma unroll
            for (int e = 0; e < 4; ++e) acc[mi][n8][e] = 0.f;

    const int T = KS * KS * 8;      // stages = taps x 8 chunks of 32 ch

    auto stage = [&](int it) {
        const int tap = it >> 3, kc = it & 7;
        const int dy = tap / KS - KS / 2, dx = tap % KS - KS / 2;
        const uint32_t bs = sb + (uint32_t)(it & 1) * 32768u;
#pragma unroll
        for (int pass = 0; pass < 2; ++pass) {
            const int idx = pass * 256 + tid;       // 0..511
            const int r = idx >> 2, gg = idx & 3;   // row 0..127, 16B granule 0..3
            const uint32_t so = SWZ((uint32_t)((r >> 1) * 128 + (r & 1) * 64 + gg * 16));
            // A (pixel row shifted by tap; zfill out-of-image)
            const int p = p0 + r;
            const int py = ((p >> 5) & 31) + dy, px = (p & 31) + dx;
            const bool v = ((unsigned)py < 32u) && ((unsigned)px < 32u);
            const size_t aoff = v ?
                ((size_t)((((bimg * 32 + py) << 5) + px)) * 256 + (size_t)kc * 32) * 2
                + (size_t)gg * 16 : 0;
            const uint32_t sz = v ? 16u : 0u;
            cp16(bs + so,        (const char*)Ah + aoff, sz);
            cp16(bs + 8192 + so, (const char*)Al + aoff, sz);
            // B (always valid)
            const size_t boff =
                ((size_t)(tap * 256 + nb * 128 + r) * 256 + (size_t)kc * 32) * 2
                + (size_t)gg * 16;
            cp16(bs + 16384 + so, (const char*)Bh + boff, 16u);
            cp16(bs + 24576 + so, (const char*)Bl + boff, 16u);
        }
    };

    stage(0); CP_COMMIT;

#pragma unroll 1
    for (int it = 0; it < T; ++it) {
        if (it + 1 < T) { stage(it + 1); CP_COMMIT; CP_WAIT1; }
        else            { CP_WAIT0; }
        __syncthreads();

        const uint32_t bs = sb + (uint32_t)(it & 1) * 32768u;
#pragma unroll
        for (int kk = 0; kk < 2; ++kk) {
            const int kb = kk * 32;                 // 16 bf16 = 32B within 64B row
            uint32_t ahf[2][4], alf[2][4], bhf[4][4], blf[4][4];
#pragma unroll
            for (int mi = 0; mi < 2; ++mi) {
                const int r = wm + mi * 16 + (lane & 15);
                const int cb = kb + ((lane >> 4) << 4);
                const uint32_t ad = bs + SWZ((uint32_t)((r >> 1) * 128 + (r & 1) * 64 + cb));
                LDSM4(ahf[mi], ad);
                LDSM4(alf[mi], ad + 8192);
            }
#pragma unroll
            for (int q = 0; q < 4; ++q) {
                const int r = wn + q * 16 + (lane & 7) + ((lane & 16) >> 1);
                const int cb = kb + ((lane & 8) << 1);
                const uint32_t bd = bs + 16384
                    + SWZ((uint32_t)((r >> 1) * 128 + (r & 1) * 64 + cb));
                LDSM4(bhf[q], bd);
                LDSM4(blf[q], bd + 8192);
            }
#pragma unroll
            for (int mi = 0; mi < 2; ++mi)
#pragma unroll
                for (int n8 = 0; n8 < 8; ++n8)
                    MMA16816(acc[mi][n8], ahf[mi],
                             bhf[n8 >> 1][(n8 & 1) * 2], bhf[n8 >> 1][(n8 & 1) * 2 + 1]);
#pragma unroll
            for (int mi = 0; mi < 2; ++mi)
#pragma unroll
                for (int n8 = 0; n8 < 8; ++n8)
                    MMA16816(acc[mi][n8], ahf[mi],
                             blf[n8 >> 1][(n8 & 1) * 2], blf[n8 >> 1][(n8 & 1) * 2 + 1]);
#pragma unroll
            for (int mi = 0; mi < 2; ++mi)
#pragma unroll
                for (int n8 = 0; n8 < 8; ++n8)
                    MMA16816(acc[mi][n8], alf[mi],
                             bhf[n8 >> 1][(n8 & 1) * 2], bhf[n8 >> 1][(n8 & 1) * 2 + 1]);
        }
        __syncthreads();
    }

    // epilogue (R9-proven direct scatter): c0=(g,2t) c1=(g,2t+1) c2=(g+8,2t) c3=(g+8,2t+1)
    const int g = lane >> 2, t2 = (lane & 3) * 2;
    if (TROUT) {
#pragma unroll
        for (int mi = 0; mi < 2; ++mi)
#pragma unroll
            for (int n8 = 0; n8 < 8; ++n8) {
                const int c = nb * 128 + wn + n8 * 8 + t2;
                const int r0 = (p0 + wm + mi * 16 + g) & 1023;
                const int r1 = r0 + 8;
                const float b0v = bias[c], b1v = bias[c + 1];
                float* C0 = C + ((size_t)(bimg * 256 + c) << 10);
                float* C1 = C + ((size_t)(bimg * 256 + c + 1) << 10);
                C0[r0] = acc[mi][n8][0] + b0v;
                C1[r0] = acc[mi][n8][1] + b1v;
                C0[r1] = acc[mi][n8][2] + b0v;
                C1[r1] = acc[mi][n8][3] + b1v;
            }
    } else {
#pragma unroll
        for (int mi = 0; mi < 2; ++mi)
#pragma unroll
            for (int n8 = 0; n8 < 8; ++n8) {
                const int c = nb * 128 + wn + n8 * 8 + t2;
                const int r0 = p0 + wm + mi * 16 + g;
                *(float2*)(C + (size_t)r0 * 256 + c) =
                    make_float2(acc[mi][n8][0], acc[mi][n8][1]);
                *(float2*)(C + (size_t)(r0 + 8) * 256 + c) =
                    make_float2(acc[mi][n8][2], acc[mi][n8][3]);
            }
    }
}

// ---------- attention (f32x2; exp2-domain scores; emits bf16 hi/lo) ----------
__global__ __launch_bounds__(512, 1)
void attn_kernel(const float* __restrict__ qT, const float* __restrict__ kT,
                 const float* __restrict__ vT,
                 __nv_bfloat16* __restrict__ aoh, __nv_bfloat16* __restrict__ aol)
{
    extern __shared__ float sm[];
    float* Ks = sm;            // [1024][16]
    float* Vs = sm + 16384;    // [1024][16]
    __shared__ int s_maxn;

    const int bh = blockIdx.x;
    const int b = bh >> 4, a = bh & 15;
    const int tid = threadIdx.x;

    const float* kb = kT + ((b * 256 + a * 16) << 10);
    const float* vb = vT + ((b * 256 + a * 16) << 10);
    const float* qslab = qT + ((b * 256 + a * 16) << 10);

    for (int i = tid; i < 4096; i += 512) {
        ((float4*)Ks)[i] = ((const float4*)kb)[i];
        ((float4*)Vs)[i] = ((const float4*)vb)[i];
    }
    if (tid == 0) s_maxn = 0;
    __syncthreads();

    float mx = 0.f;
    for (int t = tid; t < 1024; t += 512) {
        const float* kr = Ks + t * 16;
        float s = 0.f;
#pragma unroll
        for (int d = 0; d < 16; ++d) s = fmaf(kr[d], kr[d], s);
        mx = fmaxf(mx, s);
    }
#pragma unroll
    for (int off = 16; off; off >>= 1) mx = fmaxf(mx, __shfl_xor_sync(0xffffffffu, mx, off));
    if ((tid & 31) == 0) atomicMax(&s_maxn, __float_as_int(mx));
    __syncthreads();
    const float kn = sqrtf(__int_as_float(s_maxn));

    for (int qi = 0; qi < 2; ++qi) {
        const int t = qi * 512 + tid;

        ull q2[8];
        {
            const ulonglong2* qp = (const ulonglong2*)(qslab + t * 16);
            ulonglong2 u0 = qp[0], u1 = qp[1], u2 = qp[2], u3 = qp[3];
            q2[0] = u0.x; q2[1] = u0.y; q2[2] = u1.x; q2[3] = u1.y;
            q2[4] = u2.x; q2[5] = u2.y; q2[6] = u3.x; q2[7] = u3.y;
        }
        // fold 0.25 * log2(e) into q: scores live in exp2 domain
        const float QS = 0.25f * 1.4426950408889634f;
        const ull qs = pk(QS, QS);
#pragma unroll
        for (int j = 0; j < 8; ++j) q2[j] = mul2(q2[j], qs);

        ull n0 = 0ull, n1 = 0ull;
#pragma unroll
        for (int j = 0; j < 8; j += 2) {
            n0 = fma2(q2[j], q2[j], n0);
            n1 = fma2(q2[j + 1], q2[j + 1], n1);
        }
        n0 = add2(n0, n1);
        float nl, nh; upk(n0, nl, nh);
        const float M = sqrtf(nl + nh) * kn;   // Cauchy-Schwarz bound in exp2 domain

        ull acc[8];
#pragma unroll
        for (int j = 0; j < 8; ++j) acc[j] = 0ull;
        float l = 0.f;

#pragma unroll 2
        for (int m = 0; m < 1024; ++m) {
            const ulonglong2* kp = (const ulonglong2*)(Ks + m * 16);
            ulonglong2 k0 = kp[0], k1 = kp[1], k2 = kp[2], k3 = kp[3];
            ull c0 = 0ull, c1 = 0ull;
            c0 = fma2(q2[0], k0.x, c0); c1 = fma2(q2[1], k0.y, c1);
            c0 = fma2(q2[2], k1.x, c0); c1 = fma2(q2[3], k1.y, c1);
            c0 = fma2(q2[4], k2.x, c0); c1 = fma2(q2[5], k2.y, c1);
            c0 = fma2(q2[6], k3.x, c0); c1 = fma2(q2[7], k3.y, c1);
            c0 = add2(c0, c1);
            float sl, sh; upk(c0, sl, sh);
            const float p = exp2f(sl + sh - M);   // arg <= 0, no overflow
            l += p;

            const ulonglong2* vp = (const ulonglong2*)(Vs + m * 16);
            ulonglong2 v0 = vp[0], v1 = vp[1], v2 = vp[2], v3 = vp[3];
            const ull pp = pk(p, p);
            acc[0] = fma2(pp, v0.x, acc[0]); acc[1] = fma2(pp, v0.y, acc[1]);
            acc[2] = fma2(pp, v1.x, acc[2]); acc[3] = fma2(pp, v1.y, acc[3]);
            acc[4] = fma2(pp, v2.x, acc[4]); acc[5] = fma2(pp, v2.y, acc[5]);
            acc[6] = fma2(pp, v3.x, acc[6]); acc[7] = fma2(pp, v3.y, acc[7]);
        }

        const float inv = 1.f / l;
        float o[16];
#pragma unroll
        for (int j = 0; j < 8; ++j) upk(acc[j], o[2 * j], o[2 * j + 1]);
        const size_t base = ((size_t)((b << 10) + t)) * 256 + a * 16;
        __nv_bfloat162* dh = (__nv_bfloat162*)(aoh + base);
        __nv_bfloat162* dl = (__nv_bfloat162*)(aol + base);
#pragma unroll
        for (int j = 0; j < 8; ++j) {
            float v0 = o[2 * j] * inv, v1 = o[2 * j + 1] * inv;
            __nv_bfloat16 h0 = __float2bfloat16(v0), h1 = __float2bfloat16(v1);
            __nv_bfloat16 l0 = __float2bfloat16(v0 - __bfloat162float(h0));
            __nv_bfloat16 l1 = __float2bfloat16(v1 - __bfloat162float(h1));
            dh[j] = __halves2bfloat162(h0, h1);
            dl[j] = __halves2bfloat162(l0, l1);
        }
    }
}

// ---------- launch ----------
extern "C" void kernel_launch(void* const* d_in, const int* in_sizes, int n_in,
                              void* d_out, int out_size)
{
    (void)in_sizes; (void)out_size;
    if (n_in < 8) return;

    const float* x  = (const float*)d_in[0];
    const float* w3 = (const float*)d_in[1];
    const float* b3 = (const float*)d_in[2];
    const float* w5 = (const float*)d_in[3];
    const float* b5 = (const float*)d_in[4];
    const float* w7 = (const float*)d_in[5];
    const float* b7 = (const float*)d_in[6];
    const float* wp = (const float*)d_in[7];
    float* out = (float*)d_out;

    __nv_bfloat16 *p_xh, *p_xl, *p_w3h, *p_w3l, *p_w5h, *p_w5l, *p_w7h, *p_w7l,
                  *p_wph, *p_wpl, *p_aoh, *p_aol;
    float *p_q, *p_k, *p_v;
    cudaGetSymbolAddress((void**)&p_xh,  g_xh);  cudaGetSymbolAddress((void**)&p_xl,  g_xl);
    cudaGetSymbolAddress((void**)&p_w3h, g_w3h); cudaGetSymbolAddress((void**)&p_w3l, g_w3l);
    cudaGetSymbolAddress((void**)&p_w5h, g_w5h); cudaGetSymbolAddress((void**)&p_w5l, g_w5l);
    cudaGetSymbolAddress((void**)&p_w7h, g_w7h); cudaGetSymbolAddress((void**)&p_w7l, g_w7l);
    cudaGetSymbolAddress((void**)&p_wph, g_wph); cudaGetSymbolAddress((void**)&p_wpl, g_wpl);
    cudaGetSymbolAddress((void**)&p_aoh, g_aoh); cudaGetSymbolAddress((void**)&p_aol, g_aol);
    cudaGetSymbolAddress((void**)&p_q, g_q);
    cudaGetSymbolAddress((void**)&p_k, g_k);
    cudaGetSymbolAddress((void**)&p_v, g_v);

    const int CONV_SMEM = 2 * 32768;   // 64 KB (double-buffered 32KB stages) -> occ 2
    cudaFuncSetAttribute(conv_mma<1, true>,  cudaFuncAttributeMaxDynamicSharedMemorySize, CONV_SMEM);
    cudaFuncSetAttribute(conv_mma<3, true>,  cudaFuncAttributeMaxDynamicSharedMemorySize, CONV_SMEM);
    cudaFuncSetAttribute(conv_mma<5, true>,  cudaFuncAttributeMaxDynamicSharedMemorySize, CONV_SMEM);
    cudaFuncSetAttribute(conv_mma<1, false>, cudaFuncAttributeMaxDynamicSharedMemorySize, CONV_SMEM);
    cudaFuncSetAttribute(attn_kernel, cudaFuncAttributeMaxDynamicSharedMemorySize, 131072);

    // one fused hi/lo split over all five tensors
    fused_split<<<17408, 256>>>(x, w3, w5, w7, wp,
                                p_xh, p_xl, p_w3h, p_w3l, p_w5h, p_w5l,
                                p_w7h, p_w7l, p_wph, p_wpl);

    dim3 grid(2, 64);
    // q: 1x1 (w3), v: 3x3 (w5), k: 5x5 (w7) — names match the reference
    conv_mma<1, true><<<grid, 256, CONV_SMEM>>>(p_xh, p_xl, p_w3h, p_w3l, b3, p_q);
    conv_mma<3, true><<<grid, 256, CONV_SMEM>>>(p_xh, p_xl, p_w5h, p_w5l, b5, p_v);
    conv_mma<5, true><<<grid, 256, CONV_SMEM>>>(p_xh, p_xl, p_w7h, p_w7l, b7, p_k);

    attn_kernel<<<128, 512, 131072>>>(p_q, p_k, p_v, p_aoh, p_aol);

    conv_mma<1, false><<<grid, 256, CONV_SMEM>>>(p_aoh, p_aol, p_wph, p_wpl, nullptr, out);
}

// round 16
// speedup vs baseline: 1.0038x; 1.0038x over previous
#include <cuda_runtime.h>
#include <cuda_bf16.h>
#include <cstdint>

typedef unsigned long long ull;

// ---------- packed f32x2 helpers (attention) ----------
__device__ __forceinline__ ull fma2(ull a, ull b, ull c) {
    ull d; asm("fma.rn.f32x2 %0, %1, %2, %3;" : "=l"(d) : "l"(a), "l"(b), "l"(c)); return d;
}
__device__ __forceinline__ ull add2(ull a, ull b) {
    ull d; asm("add.rn.f32x2 %0, %1, %2;" : "=l"(d) : "l"(a), "l"(b)); return d;
}
__device__ __forceinline__ ull mul2(ull a, ull b) {
    ull d; asm("mul.rn.f32x2 %0, %1, %2;" : "=l"(d) : "l"(a), "l"(b)); return d;
}
__device__ __forceinline__ ull pk(float lo, float hi) {
    ull r; asm("mov.b64 %0, {%1, %2};" : "=l"(r) : "f"(lo), "f"(hi)); return r;
}
__device__ __forceinline__ void upk(ull v, float& lo, float& hi) {
    asm("mov.b64 {%0, %1}, %2;" : "=f"(lo), "=f"(hi) : "l"(v));
}

// ---------- warp-MMA primitives ----------
#define SWZ(o) ((uint32_t)(o) ^ ((((uint32_t)(o)) >> 3) & 0x70u))

__device__ __forceinline__ uint32_t smem_u32(const void* p) {
    uint32_t a;
    asm("{ .reg .u64 t; cvta.to.shared.u64 t, %1; cvt.u32.u64 %0, t; }" : "=r"(a) : "l"(p));
    return a;
}
__device__ __forceinline__ void cp16(uint32_t dst, const void* src, uint32_t srcsz) {
    asm volatile("cp.async.ca.shared.global [%0], [%1], 16, %2;"
                 :: "r"(dst), "l"(src), "r"(srcsz) : "memory");
}
#define CP_COMMIT asm volatile("cp.async.commit_group;" ::: "memory")
#define CP_WAIT1  asm volatile("cp.async.wait_group 1;" ::: "memory")
#define CP_WAIT0  asm volatile("cp.async.wait_group 0;" ::: "memory")

#define LDSM4(d, a) \
    asm volatile("ldmatrix.sync.aligned.m8n8.x4.shared.b16 {%0,%1,%2,%3}, [%4];" \
                 : "=r"((d)[0]), "=r"((d)[1]), "=r"((d)[2]), "=r"((d)[3]) : "r"(a))

#define MMA16816(c, a, b0, b1) \
    asm volatile("mma.sync.aligned.m16n8k16.row.col.f32.bf16.bf16.f32 " \
                 "{%0,%1,%2,%3},{%4,%5,%6,%7},{%8,%9},{%0,%1,%2,%3};" \
                 : "+f"((c)[0]), "+f"((c)[1]), "+f"((c)[2]), "+f"((c)[3]) \
                 : "r"((a)[0]), "r"((a)[1]), "r"((a)[2]), "r"((a)[3]), \
                   "r"(b0), "r"(b1))

// ---------- scratch (device globals) ----------
__device__ __align__(128) __nv_bfloat16 g_xh[2097152], g_xl[2097152];     // [pix][256]
__device__ __align__(128) __nv_bfloat16 g_w3h[65536],   g_w3l[65536];     // [tap][oc][cin]
__device__ __align__(128) __nv_bfloat16 g_w5h[589824],  g_w5l[589824];
__device__ __align__(128) __nv_bfloat16 g_w7h[1638400], g_w7l[1638400];
__device__ __align__(128) __nv_bfloat16 g_wph[65536],   g_wpl[65536];
__device__ __align__(128) float g_q[2097152], g_k[2097152], g_v[2097152]; // [b*256+ch][1024]
__device__ __align__(128) __nv_bfloat16 g_aoh[2097152], g_aol[2097152];   // [pix][256]

// ---------- one fused split kernel (all 5 tensors by flat index) ----------
__device__ __forceinline__ void wsplit(const float* w, __nv_bfloat16* wh,
                                       __nv_bfloat16* wl, int idx, int taps) {
    int o = (idx >> 8) & 255;
    int i = idx & 255;
    int t = idx >> 16;
    float f = w[(o * 256 + i) * taps + t];
    __nv_bfloat16 h = __float2bfloat16(f);
    wh[idx] = h;
    wl[idx] = __float2bfloat16(f - __bfloat162float(h));
}
__global__ void fused_split(const float* __restrict__ x,  const float* __restrict__ w3,
                            const float* __restrict__ w5, const float* __restrict__ w7,
                            const float* __restrict__ wp,
                            __nv_bfloat16* xh, __nv_bfloat16* xl,
                            __nv_bfloat16* w3h, __nv_bfloat16* w3l,
                            __nv_bfloat16* w5h, __nv_bfloat16* w5l,
                            __nv_bfloat16* w7h, __nv_bfloat16* w7l,
                            __nv_bfloat16* wph, __nv_bfloat16* wpl) {
    int i = blockIdx.x * 256 + threadIdx.x;
    if (i < 2097152) {
        float f = x[i];
        __nv_bfloat16 h = __float2bfloat16(f);
        xh[i] = h;
        xl[i] = __float2bfloat16(f - __bfloat162float(h));
    } else if (i < 2162688) {
        wsplit(w3, w3h, w3l, i - 2097152, 1);
    } else if (i < 2752512) {
        wsplit(w5, w5h, w5l, i - 2162688, 9);
    } else if (i < 4390912) {
        wsplit(w7, w7h, w7l, i - 2752512, 25);
    } else {
        wsplit(wp, wph, wpl, i - 4390912, 1);
    }
}

// ---------- HMMA implicit-GEMM conv (bf16 3-term split; tile 128x64, occ 2) ----------
// D[128 pix, 64 oc] = sum over (tap, 64-ch chunk) of Ah*Bh + Ah*Bl + Al*Bh.
// Stage 48KB: Ah@0(16K) Al@16K Bh@32K(8K) Bl@40K. Double buffer = 96KB -> 2 CTAs/SM.
// Grid (4,64)=256 CTAs. 8 warps: warp_m=wid&3 (32 rows), warp_n=wid>>2 (32 cols).
template<int KS, bool TROUT>
__global__ __launch_bounds__(256, 2)
void conv_mma(const __nv_bfloat16* __restrict__ Ah, const __nv_bfloat16* __restrict__ Al,
              const __nv_bfloat16* __restrict__ Bh, const __nv_bfloat16* __restrict__ Bl,
              const float* __restrict__ bias, float* __restrict__ C)
{
    extern __shared__ char smem[];
    const uint32_t sb = smem_u32(smem);
    const int tid = threadIdx.x, wid = tid >> 5, lane = tid & 31;
    const int nb = blockIdx.x;      // oc block of 64 (0..3)
    const int mb = blockIdx.y;      // pixel block of 128 (0..63)
    const int p0 = mb * 128, bimg = p0 >> 10;
    const int wm = (wid & 3) * 32, wn = (wid >> 2) * 32;

    float acc[2][4][4];
#pragma unroll
    for (int mi = 0; mi < 2; ++mi)
#pragma unroll
        for (int n8 = 0; n8 < 4; ++n8)
#pragma unroll
            for (int e = 0; e < 4; ++e) acc[mi][n8][e] = 0.f;

    const int T = KS * KS * 4;      // stages = taps x 4 chunks of 64 ch

    auto stage = [&](int it) {
        const int tap = it >> 2, kc = it & 3;
        const int dy = tap / KS - KS / 2, dx = tap % KS - KS / 2;
        const uint32_t bs = sb + (uint32_t)(it & 1) * 49152u;
        // A: 128 rows x 8 granules (hi+lo), 4 passes
#pragma unroll
        for (int pass = 0; pass < 4; ++pass) {
            const int idx = pass * 256 + tid;       // 0..1023
            const int r = idx >> 3, gran = idx & 7;
            const uint32_t so = SWZ((uint32_t)(r * 128 + gran * 16));
            const int p = p0 + r;
            const int py = ((p >> 5) & 31) + dy, px = (p & 31) + dx;
            const bool v = ((unsigned)py < 32u) && ((unsigned)px < 32u);
            const size_t aoff = v ?
                ((size_t)((((bimg * 32 + py) << 5) + px)) * 256 + (size_t)kc * 64) * 2
                + (size_t)gran * 16 : 0;
            const uint32_t sz = v ? 16u : 0u;
            cp16(bs + so,         (const char*)Ah + aoff, sz);
            cp16(bs + 16384 + so, (const char*)Al + aoff, sz);
        }
        // B: 64 rows x 8 granules (hi+lo), 2 passes
#pragma unroll
        for (int pass = 0; pass < 2; ++pass) {
            const int idx = pass * 256 + tid;       // 0..511
            const int r = idx >> 3, gran = idx & 7; // oc row 0..63
            const uint32_t so = SWZ((uint32_t)(r * 128 + gran * 16));
            const size_t boff =
                ((size_t)(tap * 256 + nb * 64 + r) * 256 + (size_t)kc * 64) * 2
                + (size_t)gran * 16;
            cp16(bs + 32768 + so, (const char*)Bh + boff, 16u);
            cp16(bs + 40960 + so, (const char*)Bl + boff, 16u);
        }
    };

    stage(0); CP_COMMIT;

#pragma unroll 1
    for (int it = 0; it < T; ++it) {
        if (it + 1 < T) { stage(it + 1); CP_COMMIT; CP_WAIT1; }
        else            { CP_WAIT0; }
        __syncthreads();

        const uint32_t bs = sb + (uint32_t)(it & 1) * 49152u;
#pragma unroll
        for (int kk = 0; kk < 4; ++kk) {
            const int kb = kk * 32;                 // 16 bf16 = 32B
            uint32_t ahf[2][4], alf[2][4], bhf[2][4], blf[2][4];
#pragma unroll
            for (int mi = 0; mi < 2; ++mi) {
                const int r = wm + mi * 16 + (lane & 15);
                const int cb = kb + ((lane >> 4) << 4);
                const uint32_t ad = bs + SWZ((uint32_t)(r * 128 + cb));
                LDSM4(ahf[mi], ad);
                LDSM4(alf[mi], ad + 16384);
            }
#pragma unroll
            for (int q = 0; q < 2; ++q) {
                const int r = wn + q * 16 + (lane & 7) + ((lane & 16) >> 1);
                const int cb = kb + ((lane & 8) << 1);
                const uint32_t bd = bs + 32768 + SWZ((uint32_t)(r * 128 + cb));
                LDSM4(bhf[q], bd);
                LDSM4(blf[q], bd + 8192);
            }
#pragma unroll
            for (int mi = 0; mi < 2; ++mi)
#pragma unroll
                for (int n8 = 0; n8 < 4; ++n8)
                    MMA16816(acc[mi][n8], ahf[mi],
                             bhf[n8 >> 1][(n8 & 1) * 2], bhf[n8 >> 1][(n8 & 1) * 2 + 1]);
#pragma unroll
            for (int mi = 0; mi < 2; ++mi)
#pragma unroll
                for (int n8 = 0; n8 < 4; ++n8)
                    MMA16816(acc[mi][n8], ahf[mi],
                             blf[n8 >> 1][(n8 & 1) * 2], blf[n8 >> 1][(n8 & 1) * 2 + 1]);
#pragma unroll
            for (int mi = 0; mi < 2; ++mi)
#pragma unroll
                for (int n8 = 0; n8 < 4; ++n8)
                    MMA16816(acc[mi][n8], alf[mi],
                             bhf[n8 >> 1][(n8 & 1) * 2], bhf[n8 >> 1][(n8 & 1) * 2 + 1]);
        }
        __syncthreads();
    }

    // epilogue: D fragment c0=(g,2t) c1=(g,2t+1) c2=(g+8,2t) c3=(g+8,2t+1)
    const int g = lane >> 2, t2 = (lane & 3) * 2;
    if (TROUT) {
#pragma unroll
        for (int mi = 0; mi < 2; ++mi)
#pragma unroll
            for (int n8 = 0; n8 < 4; ++n8) {
                const int c = nb * 64 + wn + n8 * 8 + t2;
                const int r0 = (p0 + wm + mi * 16 + g) & 1023;
                const int r1 = r0 + 8;
                const float b0v = bias[c], b1v = bias[c + 1];
                float* C0 = C + ((size_t)(bimg * 256 + c) << 10);
                float* C1 = C + ((size_t)(bimg * 256 + c + 1) << 10);
                C0[r0] = acc[mi][n8][0] + b0v;
                C1[r0] = acc[mi][n8][1] + b1v;
                C0[r1] = acc[mi][n8][2] + b0v;
                C1[r1] = acc[mi][n8][3] + b1v;
            }
    } else {
#pragma unroll
        for (int mi = 0; mi < 2; ++mi)
#pragma unroll
            for (int n8 = 0; n8 < 4; ++n8) {
                const int c = nb * 64 + wn + n8 * 8 + t2;
                const int r0 = p0 + wm + mi * 16 + g;
                *(float2*)(C + (size_t)r0 * 256 + c) =
                    make_float2(acc[mi][n8][0], acc[mi][n8][1]);
                *(float2*)(C + (size_t)(r0 + 8) * 256 + c) =
                    make_float2(acc[mi][n8][2], acc[mi][n8][3]);
            }
    }
}

// ---------- attention (f32x2; exp2-domain scores; emits bf16 hi/lo) ----------
__global__ __launch_bounds__(512, 1)
void attn_kernel(const float* __restrict__ qT, const float* __restrict__ kT,
                 const float* __restrict__ vT,
                 __nv_bfloat16* __restrict__ aoh, __nv_bfloat16* __restrict__ aol)
{
    extern __shared__ float sm[];
    float* Ks = sm;            // [1024][16]
    float* Vs = sm + 16384;    // [1024][16]
    __shared__ int s_maxn;

    const int bh = blockIdx.x;
    const int b = bh >> 4, a = bh & 15;
    const int tid = threadIdx.x;

    const float* kb = kT + ((b * 256 + a * 16) << 10);
    const float* vb = vT + ((b * 256 + a * 16) << 10);
    const float* qslab = qT + ((b * 256 + a * 16) << 10);

    for (int i = tid; i < 4096; i += 512) {
        ((float4*)Ks)[i] = ((const float4*)kb)[i];
        ((float4*)Vs)[i] = ((const float4*)vb)[i];
    }
    if (tid == 0) s_maxn = 0;
    __syncthreads();

    float mx = 0.f;
    for (int t = tid; t < 1024; t += 512) {
        const float* kr = Ks + t * 16;
        float s = 0.f;
#pragma unroll
        for (int d = 0; d < 16; ++d) s = fmaf(kr[d], kr[d], s);
        mx = fmaxf(mx, s);
    }
#pragma unroll
    for (int off = 16; off; off >>= 1) mx = fmaxf(mx, __shfl_xor_sync(0xffffffffu, mx, off));
    if ((tid & 31) == 0) atomicMax(&s_maxn, __float_as_int(mx));
    __syncthreads();
    const float kn = sqrtf(__int_as_float(s_maxn));

    for (int qi = 0; qi < 2; ++qi) {
        const int t = qi * 512 + tid;

        ull q2[8];
        {
            const ulonglong2* qp = (const ulonglong2*)(qslab + t * 16);
            ulonglong2 u0 = qp[0], u1 = qp[1], u2 = qp[2], u3 = qp[3];
            q2[0] = u0.x; q2[1] = u0.y; q2[2] = u1.x; q2[3] = u1.y;
            q2[4] = u2.x; q2[5] = u2.y; q2[6] = u3.x; q2[7] = u3.y;
        }
        // fold 0.25 * log2(e) into q: scores live in exp2 domain
        const float QS = 0.25f * 1.4426950408889634f;
        const ull qs = pk(QS, QS);
#pragma unroll
        for (int j = 0; j < 8; ++j) q2[j] = mul2(q2[j], qs);

        ull n0 = 0ull, n1 = 0ull;
#pragma unroll
        for (int j = 0; j < 8; j += 2) {
            n0 = fma2(q2[j], q2[j], n0);
            n1 = fma2(q2[j + 1], q2[j + 1], n1);
        }
        n0 = add2(n0, n1);
        float nl, nh; upk(n0, nl, nh);
        const float M = sqrtf(nl + nh) * kn;   // Cauchy-Schwarz bound in exp2 domain

        ull acc[8];
#pragma unroll
        for (int j = 0; j < 8; ++j) acc[j] = 0ull;
        float l = 0.f;

#pragma unroll 2
        for (int m = 0; m < 1024; ++m) {
            const ulonglong2* kp = (const ulonglong2*)(Ks + m * 16);
            ulonglong2 k0 = kp[0], k1 = kp[1], k2 = kp[2], k3 = kp[3];
            ull c0 = 0ull, c1 = 0ull;
            c0 = fma2(q2[0], k0.x, c0); c1 = fma2(q2[1], k0.y, c1);
            c0 = fma2(q2[2], k1.x, c0); c1 = fma2(q2[3], k1.y, c1);
            c0 = fma2(q2[4], k2.x, c0); c1 = fma2(q2[5], k2.y, c1);
            c0 = fma2(q2[6], k3.x, c0); c1 = fma2(q2[7], k3.y, c1);
            c0 = add2(c0, c1);
            float sl, sh; upk(c0, sl, sh);
            const float p = exp2f(sl + sh - M);   // arg <= 0, no overflow
            l += p;

            const ulonglong2* vp = (const ulonglong2*)(Vs + m * 16);
            ulonglong2 v0 = vp[0], v1 = vp[1], v2 = vp[2], v3 = vp[3];
            const ull pp = pk(p, p);
            acc[0] = fma2(pp, v0.x, acc[0]); acc[1] = fma2(pp, v0.y, acc[1]);
            acc[2] = fma2(pp, v1.x, acc[2]); acc[3] = fma2(pp, v1.y, acc[3]);
            acc[4] = fma2(pp, v2.x, acc[4]); acc[5] = fma2(pp, v2.y, acc[5]);
            acc[6] = fma2(pp, v3.x, acc[6]); acc[7] = fma2(pp, v3.y, acc[7]);
        }

        const float inv = 1.f / l;
        float o[16];
#pragma unroll
        for (int j = 0; j < 8; ++j) upk(acc[j], o[2 * j], o[2 * j + 1]);
        const size_t base = ((size_t)((b << 10) + t)) * 256 + a * 16;
        __nv_bfloat162* dh = (__nv_bfloat162*)(aoh + base);
        __nv_bfloat162* dl = (__nv_bfloat162*)(aol + base);
#pragma unroll
        for (int j = 0; j < 8; ++j) {
            float v0 = o[2 * j] * inv, v1 = o[2 * j + 1] * inv;
            __nv_bfloat16 h0 = __float2bfloat16(v0), h1 = __float2bfloat16(v1);
            __nv_bfloat16 l0 = __float2bfloat16(v0 - __bfloat162float(h0));
            __nv_bfloat16 l1 = __float2bfloat16(v1 - __bfloat162float(h1));
            dh[j] = __halves2bfloat162(h0, h1);
            dl[j] = __halves2bfloat162(l0, l1);
        }
    }
}

// ---------- launch ----------
extern "C" void kernel_launch(void* const* d_in, const int* in_sizes, int n_in,
                              void* d_out, int out_size)
{
    (void)in_sizes; (void)out_size;
    if (n_in < 8) return;

    const float* x  = (const float*)d_in[0];
    const float* w3 = (const float*)d_in[1];
    const float* b3 = (const float*)d_in[2];
    const float* w5 = (const float*)d_in[3];
    const float* b5 = (const float*)d_in[4];
    const float* w7 = (const float*)d_in[5];
    const float* b7 = (const float*)d_in[6];
    const float* wp = (const float*)d_in[7];
    float* out = (float*)d_out;

    __nv_bfloat16 *p_xh, *p_xl, *p_w3h, *p_w3l, *p_w5h, *p_w5l, *p_w7h, *p_w7l,
                  *p_wph, *p_wpl, *p_aoh, *p_aol;
    float *p_q, *p_k, *p_v;
    cudaGetSymbolAddress((void**)&p_xh,  g_xh);  cudaGetSymbolAddress((void**)&p_xl,  g_xl);
    cudaGetSymbolAddress((void**)&p_w3h, g_w3h); cudaGetSymbolAddress((void**)&p_w3l, g_w3l);
    cudaGetSymbolAddress((void**)&p_w5h, g_w5h); cudaGetSymbolAddress((void**)&p_w5l, g_w5l);
    cudaGetSymbolAddress((void**)&p_w7h, g_w7h); cudaGetSymbolAddress((void**)&p_w7l, g_w7l);
    cudaGetSymbolAddress((void**)&p_wph, g_wph); cudaGetSymbolAddress((void**)&p_wpl, g_wpl);
    cudaGetSymbolAddress((void**)&p_aoh, g_aoh); cudaGetSymbolAddress((void**)&p_aol, g_aol);
    cudaGetSymbolAddress((void**)&p_q, g_q);
    cudaGetSymbolAddress((void**)&p_k, g_k);
    cudaGetSymbolAddress((void**)&p_v, g_v);

    const int CONV_SMEM = 2 * 49152;   // 96 KB double-buffered -> 2 CTAs/SM (192KB)
    cudaFuncSetAttribute(conv_mma<1, true>,  cudaFuncAttributeMaxDynamicSharedMemorySize, CONV_SMEM);
    cudaFuncSetAttribute(conv_mma<3, true>,  cudaFuncAttributeMaxDynamicSharedMemorySize, CONV_SMEM);
    cudaFuncSetAttribute(conv_mma<5, true>,  cudaFuncAttributeMaxDynamicSharedMemorySize, CONV_SMEM);
    cudaFuncSetAttribute(conv_mma<1, false>, cudaFuncAttributeMaxDynamicSharedMemorySize, CONV_SMEM);
    cudaFuncSetAttribute(attn_kernel, cudaFuncAttributeMaxDynamicSharedMemorySize, 131072);

    // one fused hi/lo split over all five tensors
    fused_split<<<17408, 256>>>(x, w3, w5, w7, wp,
                                p_xh, p_xl, p_w3h, p_w3l, p_w5h, p_w5l,
                                p_w7h, p_w7l, p_wph, p_wpl);

    dim3 grid(4, 64);   // 256 CTAs: oc blocks of 64 x pixel blocks of 128
    // q: 1x1 (w3), v: 3x3 (w5), k: 5x5 (w7) — names match the reference
    conv_mma<1, true><<<grid, 256, CONV_SMEM>>>(p_xh, p_xl, p_w3h, p_w3l, b3, p_q);
    conv_mma<3, true><<<grid, 256, CONV_SMEM>>>(p_xh, p_xl, p_w5h, p_w5l, b5, p_v);
    conv_mma<5, true><<<grid, 256, CONV_SMEM>>>(p_xh, p_xl, p_w7h, p_w7l, b7, p_k);

    attn_kernel<<<128, 512, 131072>>>(p_q, p_k, p_v, p_aoh, p_aol);

    conv_mma<1, false><<<grid, 256, CONV_SMEM>>>(p_aoh, p_aol, p_wph, p_wpl, nullptr, out);
}

// round 17
// speedup vs baseline: 1.0843x; 1.0802x over previous
#include <cuda_runtime.h>
#include <cstdint>

typedef unsigned long long ull;

// ---------- packed f32x2 helpers (attention) ----------
__device__ __forceinline__ ull fma2(ull a, ull b, ull c) {
    ull d; asm("fma.rn.f32x2 %0, %1, %2, %3;" : "=l"(d) : "l"(a), "l"(b), "l"(c)); return d;
}
__device__ __forceinline__ ull add2(ull a, ull b) {
    ull d; asm("add.rn.f32x2 %0, %1, %2;" : "=l"(d) : "l"(a), "l"(b)); return d;
}
__device__ __forceinline__ ull mul2(ull a, ull b) {
    ull d; asm("mul.rn.f32x2 %0, %1, %2;" : "=l"(d) : "l"(a), "l"(b)); return d;
}
__device__ __forceinline__ ull pk(float lo, float hi) {
    ull r; asm("mov.b64 %0, {%1, %2};" : "=l"(r) : "f"(lo), "f"(hi)); return r;
}
__device__ __forceinline__ void upk(ull v, float& lo, float& hi) {
    asm("mov.b64 {%0, %1}, %2;" : "=f"(lo), "=f"(hi) : "l"(v));
}

// ---------- warp-MMA primitives ----------
#define SWZ(o) ((uint32_t)(o) ^ ((((uint32_t)(o)) >> 3) & 0x70u))

__device__ __forceinline__ uint32_t smem_u32(const void* p) {
    uint32_t a;
    asm("{ .reg .u64 t; cvta.to.shared.u64 t, %1; cvt.u32.u64 %0, t; }" : "=r"(a) : "l"(p));
    return a;
}
__device__ __forceinline__ void cp16(uint32_t dst, const void* src, uint32_t srcsz) {
    asm volatile("cp.async.ca.shared.global [%0], [%1], 16, %2;"
                 :: "r"(dst), "l"(src), "r"(srcsz) : "memory");
}
#define CP_COMMIT asm volatile("cp.async.commit_group;" ::: "memory")
#define CP_WAIT1  asm volatile("cp.async.wait_group 1;" ::: "memory")
#define CP_WAIT0  asm volatile("cp.async.wait_group 0;" ::: "memory")

#define LDSM4(d, a) \
    asm volatile("ldmatrix.sync.aligned.m8n8.x4.shared.b16 {%0,%1,%2,%3}, [%4];" \
                 : "=r"((d)[0]), "=r"((d)[1]), "=r"((d)[2]), "=r"((d)[3]) : "r"(a))

// tf32 m16n8k8: A = 4 regs, B = 2 regs, f32 accum. Operands pre-rounded via cvt.rna.
#define MMA_TF32(c, a, b0, b1) \
    asm volatile("mma.sync.aligned.m16n8k8.row.col.f32.tf32.tf32.f32 " \
                 "{%0,%1,%2,%3},{%4,%5,%6,%7},{%8,%9},{%0,%1,%2,%3};" \
                 : "+f"((c)[0]), "+f"((c)[1]), "+f"((c)[2]), "+f"((c)[3]) \
                 : "r"((a)[0]), "r"((a)[1]), "r"((a)[2]), "r"((a)[3]), \
                   "r"(b0), "r"(b1))

// round-to-nearest tf32 (low 13 mantissa bits zeroed) — removes truncation bias
__device__ __forceinline__ float rna(float f) {
    uint32_t u; asm("cvt.rna.tf32.f32 %0, %1;" : "=r"(u) : "f"(f));
    return __uint_as_float(u);
}

// ---------- scratch (device globals, all f32) ----------
__device__ __align__(128) float g_xr[2097152];                 // x rounded, [pix][256]
__device__ __align__(128) float g_wt3[65536];                  // [tap][oc][cin], rounded
__device__ __align__(128) float g_wt5[589824];
__device__ __align__(128) float g_wt7[1638400];
__device__ __align__(128) float g_wtp[65536];
__device__ __align__(128) float g_q[2097152], g_k[2097152], g_v[2097152]; // [b*256+ch][1024]
__device__ __align__(128) float g_ao[2097152];                 // attn out, rounded, [pix][256]

// ---------- one prep kernel: round x + transpose/round all 4 weights ----------
__device__ __forceinline__ void wprep(const float* w, float* wt, int idx, int taps) {
    int o = (idx >> 8) & 255;
    int i = idx & 255;
    int t = idx >> 16;
    wt[idx] = rna(w[(o * 256 + i) * taps + t]);
}
__global__ void prep(const float* __restrict__ x,  const float* __restrict__ w3,
                     const float* __restrict__ w5, const float* __restrict__ w7,
                     const float* __restrict__ wp,
                     float* xr, float* wt3, float* wt5, float* wt7, float* wtp) {
    int i = blockIdx.x * 256 + threadIdx.x;
    if (i < 2097152)       xr[i] = rna(x[i]);
    else if (i < 2162688)  wprep(w3, wt3, i - 2097152, 1);
    else if (i < 2752512)  wprep(w5, wt5, i - 2162688, 9);
    else if (i < 4390912)  wprep(w7, wt7, i - 2752512, 25);
    else                   wprep(wp, wtp, i - 4390912, 1);
}

// ---------- tf32 implicit-GEMM conv (single-pass; tile 128x64, occ 2) ----------
// D[128 pix, 64 oc] = sum over (tap, 64-ch chunk) of A*B in tf32 (pre-rounded f32).
// Stage 48KB: A plane0@0, plane1@16K (each 128 rows x 128B = 32 cin f32);
//             B plane0@32K, plane1@40K (64 rows x 128B each). Double buffer = 96KB.
// Grid (4,64)=256 CTAs, 2 CTAs/SM. 8 warps: warp_m=wid&3 (32 rows), warp_n=wid>>2 (32 oc).
template<int KS, bool TROUT>
__global__ __launch_bounds__(256, 2)
void conv_mma(const float* __restrict__ A, const float* __restrict__ B,
              const float* __restrict__ bias, float* __restrict__ C)
{
    extern __shared__ char smem[];
    const uint32_t sb = smem_u32(smem);
    const int tid = threadIdx.x, wid = tid >> 5, lane = tid & 31;
    const int nb = blockIdx.x;      // oc block of 64 (0..3)
    const int mb = blockIdx.y;      // pixel block of 128 (0..63)
    const int p0 = mb * 128, bimg = p0 >> 10;
    const int wm = (wid & 3) * 32, wn = (wid >> 2) * 32;

    float acc[2][4][4];
#pragma unroll
    for (int mi = 0; mi < 2; ++mi)
#pragma unroll
        for (int n8 = 0; n8 < 4; ++n8)
#pragma unroll
            for (int e = 0; e < 4; ++e) acc[mi][n8][e] = 0.f;

    const int T = KS * KS * 4;      // stages = taps x 4 chunks of 64 ch

    auto stage = [&](int it) {
        const int tap = it >> 2, kc = it & 3;
        const int dy = tap / KS - KS / 2, dx = tap % KS - KS / 2;
        const uint32_t bs = sb + (uint32_t)(it & 1) * 49152u;
        // A: 128 rows x 2 planes x 8 granules(16B) = 2048 cp16, 8 passes
#pragma unroll
        for (int pass = 0; pass < 8; ++pass) {
            const int idx = pass * 256 + tid;
            const int r = idx >> 4, q16 = idx & 15;
            const int pl = q16 >> 3, g = q16 & 7;
            const int p = p0 + r;
            const int py = ((p >> 5) & 31) + dy, px = (p & 31) + dx;
            const bool v = ((unsigned)py < 32u) && ((unsigned)px < 32u);
            const size_t aoff = v ?
                ((size_t)((((bimg * 32 + py) << 5) + px)) * 256
                 + (size_t)kc * 64 + (size_t)pl * 32 + (size_t)g * 4) * 4 : 0;
            cp16(bs + pl * 16384u + SWZ((uint32_t)(r * 128 + g * 16)),
                 (const char*)A + aoff, v ? 16u : 0u);
        }
        // B: 64 rows x 2 planes x 8 granules = 1024 cp16, 4 passes
#pragma unroll
        for (int pass = 0; pass < 4; ++pass) {
            const int idx = pass * 256 + tid;
            const int r = idx >> 4, q16 = idx & 15;
            const int pl = q16 >> 3, g = q16 & 7;
            const size_t boff =
                ((size_t)(tap * 256 + nb * 64 + r) * 256
                 + (size_t)kc * 64 + (size_t)pl * 32 + (size_t)g * 4) * 4;
            cp16(bs + 32768u + pl * 8192u + SWZ((uint32_t)(r * 128 + g * 16)),
                 (const char*)B + boff, 16u);
        }
    };

    stage(0); CP_COMMIT;

#pragma unroll 1
    for (int it = 0; it < T; ++it) {
        if (it + 1 < T) { stage(it + 1); CP_COMMIT; CP_WAIT1; }
        else            { CP_WAIT0; }
        __syncthreads();

        const uint32_t bs = sb + (uint32_t)(it & 1) * 49152u;
#pragma unroll
        for (int s = 0; s < 8; ++s) {           // 8 k8-steps over the 64-ch chunk
            const int pl = s >> 2;
            const int cb = (s & 3) * 32;        // 8 f32 = 32B per k8 step
            uint32_t af[2][4], bf[2][4];
            // A fragments: tiles (rows0-7,c0-3)(rows8-15,c0-3)(rows0-7,c4-7)(rows8-15,c4-7)
#pragma unroll
            for (int mi = 0; mi < 2; ++mi) {
                const int r = wm + mi * 16 + (lane & 15);
                const int col = cb + ((lane >> 4) << 4);
                LDSM4(af[mi], bs + pl * 16384u + SWZ((uint32_t)(r * 128 + col)));
            }
            // B fragments: per q: tiles (n0-7,b0)(n0-7,b1)(n8-15,b0)(n8-15,b1)
#pragma unroll
            for (int q = 0; q < 2; ++q) {
                const int t = lane >> 3;
                const int n = wn + q * 16 + (t >> 1) * 8 + (lane & 7);
                const int col = cb + (t & 1) * 16;
                LDSM4(bf[q], bs + 32768u + pl * 8192u + SWZ((uint32_t)(n * 128 + col)));
            }
#pragma unroll
            for (int mi = 0; mi < 2; ++mi)
#pragma unroll
                for (int n8 = 0; n8 < 4; ++n8)
                    MMA_TF32(acc[mi][n8], af[mi],
                             bf[n8 >> 1][(n8 & 1) * 2], bf[n8 >> 1][(n8 & 1) * 2 + 1]);
        }
        __syncthreads();
    }

    // epilogue: D fragment c0=(g,2t) c1=(g,2t+1) c2=(g+8,2t) c3=(g+8,2t+1)
    const int g = lane >> 2, t2 = (lane & 3) * 2;
    if (TROUT) {
#pragma unroll
        for (int mi = 0; mi < 2; ++mi)
#pragma unroll
            for (int n8 = 0; n8 < 4; ++n8) {
                const int c = nb * 64 + wn + n8 * 8 + t2;
                const int r0 = (p0 + wm + mi * 16 + g) & 1023;
                const int r1 = r0 + 8;
                const float b0v = bias[c], b1v = bias[c + 1];
                float* C0 = C + ((size_t)(bimg * 256 + c) << 10);
                float* C1 = C + ((size_t)(bimg * 256 + c + 1) << 10);
                C0[r0] = acc[mi][n8][0] + b0v;
                C1[r0] = acc[mi][n8][1] + b1v;
                C0[r1] = acc[mi][n8][2] + b0v;
                C1[r1] = acc[mi][n8][3] + b1v;
            }
    } else {
#pragma unroll
        for (int mi = 0; mi < 2; ++mi)
#pragma unroll
            for (int n8 = 0; n8 < 4; ++n8) {
                const int c = nb * 64 + wn + n8 * 8 + t2;
                const int r0 = p0 + wm + mi * 16 + g;
                *(float2*)(C + (size_t)r0 * 256 + c) =
                    make_float2(acc[mi][n8][0], acc[mi][n8][1]);
                *(float2*)(C + (size_t)(r0 + 8) * 256 + c) =
                    make_float2(acc[mi][n8][2], acc[mi][n8][3]);
            }
    }
}

// ---------- attention (f32x2; exp2-domain; emits tf32-rounded f32 [pix][256]) ----------
__global__ __launch_bounds__(512, 1)
void attn_kernel(const float* __restrict__ qT, const float* __restrict__ kT,
                 const float* __restrict__ vT, float* __restrict__ ao)
{
    extern __shared__ float sm[];
    float* Ks = sm;            // [1024][16]
    float* Vs = sm + 16384;    // [1024][16]
    __shared__ int s_maxn;

    const int bh = blockIdx.x;
    const int b = bh >> 4, a = bh & 15;
    const int tid = threadIdx.x;

    const float* kb = kT + ((b * 256 + a * 16) << 10);
    const float* vb = vT + ((b * 256 + a * 16) << 10);
    const float* qslab = qT + ((b * 256 + a * 16) << 10);

    for (int i = tid; i < 4096; i += 512) {
        ((float4*)Ks)[i] = ((const float4*)kb)[i];
        ((float4*)Vs)[i] = ((const float4*)vb)[i];
    }
    if (tid == 0) s_maxn = 0;
    __syncthreads();

    float mx = 0.f;
    for (int t = tid; t < 1024; t += 512) {
        const float* kr = Ks + t * 16;
        float s = 0.f;
#pragma unroll
        for (int d = 0; d < 16; ++d) s = fmaf(kr[d], kr[d], s);
        mx = fmaxf(mx, s);
    }
#pragma unroll
    for (int off = 16; off; off >>= 1) mx = fmaxf(mx, __shfl_xor_sync(0xffffffffu, mx, off));
    if ((tid & 31) == 0) atomicMax(&s_maxn, __float_as_int(mx));
    __syncthreads();
    const float kn = sqrtf(__int_as_float(s_maxn));

    for (int qi = 0; qi < 2; ++qi) {
        const int t = qi * 512 + tid;

        ull q2[8];
        {
            const ulonglong2* qp = (const ulonglong2*)(qslab + t * 16);
            ulonglong2 u0 = qp[0], u1 = qp[1], u2 = qp[2], u3 = qp[3];
            q2[0] = u0.x; q2[1] = u0.y; q2[2] = u1.x; q2[3] = u1.y;
            q2[4] = u2.x; q2[5] = u2.y; q2[6] = u3.x; q2[7] = u3.y;
        }
        const float QS = 0.25f * 1.4426950408889634f;   // exp2 domain
        const ull qs = pk(QS, QS);
#pragma unroll
        for (int j = 0; j < 8; ++j) q2[j] = mul2(q2[j], qs);

        ull n0 = 0ull, n1 = 0ull;
#pragma unroll
        for (int j = 0; j < 8; j += 2) {
            n0 = fma2(q2[j], q2[j], n0);
            n1 = fma2(q2[j + 1], q2[j + 1], n1);
        }
        n0 = add2(n0, n1);
        float nl, nh; upk(n0, nl, nh);
        const float M = sqrtf(nl + nh) * kn;   // Cauchy-Schwarz bound

        ull acc[8];
#pragma unroll
        for (int j = 0; j < 8; ++j) acc[j] = 0ull;
        float l = 0.f;

#pragma unroll 2
        for (int m = 0; m < 1024; ++m) {
            const ulonglong2* kp = (const ulonglong2*)(Ks + m * 16);
            ulonglong2 k0 = kp[0], k1 = kp[1], k2 = kp[2], k3 = kp[3];
            ull c0 = 0ull, c1 = 0ull;
            c0 = fma2(q2[0], k0.x, c0); c1 = fma2(q2[1], k0.y, c1);
            c0 = fma2(q2[2], k1.x, c0); c1 = fma2(q2[3], k1.y, c1);
            c0 = fma2(q2[4], k2.x, c0); c1 = fma2(q2[5], k2.y, c1);
            c0 = fma2(q2[6], k3.x, c0); c1 = fma2(q2[7], k3.y, c1);
            c0 = add2(c0, c1);
            float sl, sh; upk(c0, sl, sh);
            const float p = exp2f(sl + sh - M);   // arg <= 0
            l += p;

            const ulonglong2* vp = (const ulonglong2*)(Vs + m * 16);
            ulonglong2 v0 = vp[0], v1 = vp[1], v2 = vp[2], v3 = vp[3];
            const ull pp = pk(p, p);
            acc[0] = fma2(pp, v0.x, acc[0]); acc[1] = fma2(pp, v0.y, acc[1]);
            acc[2] = fma2(pp, v1.x, acc[2]); acc[3] = fma2(pp, v1.y, acc[3]);
            acc[4] = fma2(pp, v2.x, acc[4]); acc[5] = fma2(pp, v2.y, acc[5]);
            acc[6] = fma2(pp, v3.x, acc[6]); acc[7] = fma2(pp, v3.y, acc[7]);
        }

        const float inv = 1.f / l;
        float o[16];
#pragma unroll
        for (int j = 0; j < 8; ++j) upk(acc[j], o[2 * j], o[2 * j + 1]);
        float* dst = ao + ((size_t)((b << 10) + t)) * 256 + a * 16;
#pragma unroll
        for (int cc = 0; cc < 4; ++cc) {
            *(float4*)(dst + cc * 4) = make_float4(
                rna(o[cc * 4] * inv),     rna(o[cc * 4 + 1] * inv),
                rna(o[cc * 4 + 2] * inv), rna(o[cc * 4 + 3] * inv));
        }
    }
}

// ---------- launch ----------
extern "C" void kernel_launch(void* const* d_in, const int* in_sizes, int n_in,
                              void* d_out, int out_size)
{
    (void)in_sizes; (void)out_size;
    if (n_in < 8) return;

    const float* x  = (const float*)d_in[0];
    const float* w3 = (const float*)d_in[1];
    const float* b3 = (const float*)d_in[2];
    const float* w5 = (const float*)d_in[3];
    const float* b5 = (const float*)d_in[4];
    const float* w7 = (const float*)d_in[5];
    const float* b7 = (const float*)d_in[6];
    const float* wp = (const float*)d_in[7];
    float* out = (float*)d_out;

    float *p_xr, *p_wt3, *p_wt5, *p_wt7, *p_wtp, *p_q, *p_k, *p_v, *p_ao;
    cudaGetSymbolAddress((void**)&p_xr,  g_xr);
    cudaGetSymbolAddress((void**)&p_wt3, g_wt3);
    cudaGetSymbolAddress((void**)&p_wt5, g_wt5);
    cudaGetSymbolAddress((void**)&p_wt7, g_wt7);
    cudaGetSymbolAddress((void**)&p_wtp, g_wtp);
    cudaGetSymbolAddress((void**)&p_q,  g_q);
    cudaGetSymbolAddress((void**)&p_k,  g_k);
    cudaGetSymbolAddress((void**)&p_v,  g_v);
    cudaGetSymbolAddress((void**)&p_ao, g_ao);

    const int CONV_SMEM = 2 * 49152;   // 96 KB double-buffered -> 2 CTAs/SM
    cudaFuncSetAttribute(conv_mma<1, true>,  cudaFuncAttributeMaxDynamicSharedMemorySize, CONV_SMEM);
    cudaFuncSetAttribute(conv_mma<3, true>,  cudaFuncAttributeMaxDynamicSharedMemorySize, CONV_SMEM);
    cudaFuncSetAttribute(conv_mma<5, true>,  cudaFuncAttributeMaxDynamicSharedMemorySize, CONV_SMEM);
    cudaFuncSetAttribute(conv_mma<1, false>, cudaFuncAttributeMaxDynamicSharedMemorySize, CONV_SMEM);
    cudaFuncSetAttribute(attn_kernel, cudaFuncAttributeMaxDynamicSharedMemorySize, 131072);

    // round x + restage/round all weights (tf32 rna)
    prep<<<17408, 256>>>(x, w3, w5, w7, wp, p_xr, p_wt3, p_wt5, p_wt7, p_wtp);

    dim3 grid(4, 64);   // 256 CTAs: oc blocks of 64 x pixel blocks of 128
    // q: 1x1 (w3), v: 3x3 (w5), k: 5x5 (w7) — names match the reference
    conv_mma<1, true><<<grid, 256, CONV_SMEM>>>(p_xr, p_wt3, b3, p_q);
    conv_mma<3, true><<<grid, 256, CONV_SMEM>>>(p_xr, p_wt5, b5, p_v);
    conv_mma<5, true><<<grid, 256, CONV_SMEM>>>(p_xr, p_wt7, b7, p_k);

    attn_kernel<<<128, 512, 131072>>>(p_q, p_k, p_v, p_ao);

    conv_mma<1, false><<<grid, 256, CONV_SMEM>>>(p_ao, p_wtp, nullptr, out);
}